// round 1
// baseline (speedup 1.0000x reference)
#include <cuda_runtime.h>

// GRUAdder: B=1048576, T=4, I=2, H=16
// out = concat(hidden_table[B,4,16], sum_logits[B,4], carry[B,1], output_logits[B,5]) fp32

static constexpr int BATCH   = 1048576;
static constexpr int TT      = 4;
static constexpr int HH      = 16;
static constexpr int NP      = 24;   // 48 gate outputs packed as 24 f32x2 pairs
static constexpr int THREADS = 256;
static constexpr int ELEMS   = 2;    // batch elements per thread (share weight LDS)

typedef unsigned long long u64;

__device__ __forceinline__ u64 pack2(float lo, float hi) {
    u64 r; asm("mov.b64 %0, {%1, %2};" : "=l"(r) : "f"(lo), "f"(hi)); return r;
}
__device__ __forceinline__ float2 unpack2(u64 v) {
    float2 f; asm("mov.b64 {%0, %1}, %2;" : "=f"(f.x), "=f"(f.y) : "l"(v)); return f;
}
// packed dual-FMA: d = a * b + d  (2 fp32 MACs per instruction)
__device__ __forceinline__ void ffma2(u64 &d, u64 a, u64 b) {
    asm("fma.rn.f32x2 %0, %1, %2, %0;" : "+l"(d) : "l"(a), "l"(b));
}
__device__ __forceinline__ float sigmoid_f(float x) {
    return __fdividef(1.0f, 1.0f + __expf(-x));
}
__device__ __forceinline__ float tanh_f(float x) {
    float e = __expf(2.0f * x);
    return __fdividef(e - 1.0f, e + 1.0f);
}

__global__ void __launch_bounds__(THREADS)
gru_adder_kernel(const float* __restrict__ x,       // [B,4,2]
                 const float* __restrict__ w_ih,    // [48,2]
                 const float* __restrict__ w_hh,    // [48,16]
                 const float* __restrict__ b_ih,    // [48]
                 const float* __restrict__ b_hh,    // [48]
                 const float* __restrict__ w_sum,   // [16]
                 const float* __restrict__ b_sum,   // [1]
                 const float* __restrict__ w_carry, // [16]
                 const float* __restrict__ b_carry, // [1]
                 float* __restrict__ out,
                 long long off_hid, long long off_sum,
                 long long off_car, long long off_log)
{
    // ---- weights in shared memory (pair-packed for f32x2) ----
    __shared__ u64 s_whh[HH][NP];   // [k][pair p] -> {w_hh[2p][k], w_hh[2p+1][k]}
    __shared__ u64 s_wih[2][NP];    // [input c][pair p]
    __shared__ u64 s_bih[NP], s_bhh[NP];
    __shared__ float s_ws[HH], s_wc[HH];
    __shared__ float s_bs, s_bc;

    const int tid = threadIdx.x;
    for (int i = tid; i < HH * NP; i += THREADS) {
        int p = i % NP, k = i / NP;
        s_whh[k][p] = pack2(w_hh[(2 * p) * HH + k], w_hh[(2 * p + 1) * HH + k]);
    }
    if (tid < 2 * NP) {
        int p = tid % NP, c = tid / NP;
        s_wih[c][p] = pack2(w_ih[(2 * p) * 2 + c], w_ih[(2 * p + 1) * 2 + c]);
    }
    if (tid < NP) {
        s_bih[tid] = pack2(b_ih[2 * tid], b_ih[2 * tid + 1]);
        s_bhh[tid] = pack2(b_hh[2 * tid], b_hh[2 * tid + 1]);
    }
    if (tid < HH) { s_ws[tid] = w_sum[tid]; s_wc[tid] = w_carry[tid]; }
    if (tid == 0) { s_bs = b_sum[0]; s_bc = b_carry[0]; }
    __syncthreads();

    const int base = blockIdx.x * (THREADS * ELEMS) + tid;
    const int eA = base;
    const int eB = base + THREADS;

    // load x for both elements: 8 floats each
    const float4* xpA = reinterpret_cast<const float4*>(x + (size_t)eA * (TT * 2));
    const float4* xpB = reinterpret_cast<const float4*>(x + (size_t)eB * (TT * 2));
    float4 xA0 = xpA[0], xA1 = xpA[1];
    float4 xB0 = xpB[0], xB1 = xpB[1];
    float xsA[TT][2] = {{xA0.x, xA0.y}, {xA0.z, xA0.w}, {xA1.x, xA1.y}, {xA1.z, xA1.w}};
    float xsB[TT][2] = {{xB0.x, xB0.y}, {xB0.z, xB0.w}, {xB1.x, xB1.y}, {xB1.z, xB1.w}};

    float hA[HH], hB[HH];
#pragma unroll
    for (int k = 0; k < HH; ++k) { hA[k] = 0.0f; hB[k] = 0.0f; }

#pragma unroll
    for (int t = 0; t < TT; ++t) {
        // acc[p] = b_hh pair + sum_k h[k] * w_hh[:,k] pair
        u64 accA[NP], accB[NP];
#pragma unroll
        for (int p = 0; p < NP; ++p) { accA[p] = s_bhh[p]; accB[p] = s_bhh[p]; }

        if (t != 0) {   // t==0: h==0, hh matvec vanishes (branch folds at compile time)
#pragma unroll
            for (int k = 0; k < HH; ++k) {
                u64 ha = pack2(hA[k], hA[k]);
                u64 hb = pack2(hB[k], hB[k]);
#pragma unroll
                for (int p = 0; p < NP; ++p) {
                    u64 w = s_whh[k][p];   // one LDS serves 2 FFMA2 = 4 MACs
                    ffma2(accA[p], w, ha);
                    ffma2(accB[p], w, hb);
                }
            }
        }

        u64 px0A = pack2(xsA[t][0], xsA[t][0]), px1A = pack2(xsA[t][1], xsA[t][1]);
        u64 px0B = pack2(xsB[t][0], xsB[t][0]), px1B = pack2(xsB[t][1], xsB[t][1]);

        float rA[HH], rB[HH];
#pragma unroll
        for (int q = 0; q < 8; ++q) {          // r gate: pairs p = q
            u64 gA = s_bih[q]; ffma2(gA, s_wih[0][q], px0A); ffma2(gA, s_wih[1][q], px1A);
            u64 gB = s_bih[q]; ffma2(gB, s_wih[0][q], px0B); ffma2(gB, s_wih[1][q], px1B);
            float2 ga = unpack2(gA), aa = unpack2(accA[q]);
            float2 gb = unpack2(gB), ab = unpack2(accB[q]);
            rA[2 * q] = sigmoid_f(ga.x + aa.x); rA[2 * q + 1] = sigmoid_f(ga.y + aa.y);
            rB[2 * q] = sigmoid_f(gb.x + ab.x); rB[2 * q + 1] = sigmoid_f(gb.y + ab.y);
        }
#pragma unroll
        for (int q = 0; q < 8; ++q) {          // z pairs p=8+q, n pairs p=16+q
            int pz = 8 + q, pn = 16 + q;
            u64 gzA = s_bih[pz]; ffma2(gzA, s_wih[0][pz], px0A); ffma2(gzA, s_wih[1][pz], px1A);
            u64 gnA = s_bih[pn]; ffma2(gnA, s_wih[0][pn], px0A); ffma2(gnA, s_wih[1][pn], px1A);
            u64 gzB = s_bih[pz]; ffma2(gzB, s_wih[0][pz], px0B); ffma2(gzB, s_wih[1][pz], px1B);
            u64 gnB = s_bih[pn]; ffma2(gnB, s_wih[0][pn], px0B); ffma2(gnB, s_wih[1][pn], px1B);

            float2 za = unpack2(gzA), aza = unpack2(accA[pz]);
            float2 na = unpack2(gnA), ana = unpack2(accA[pn]);
            float z0 = sigmoid_f(za.x + aza.x), z1 = sigmoid_f(za.y + aza.y);
            float n0 = tanh_f(na.x + rA[2 * q] * ana.x);
            float n1 = tanh_f(na.y + rA[2 * q + 1] * ana.y);
            hA[2 * q]     = n0 + z0 * (hA[2 * q] - n0);
            hA[2 * q + 1] = n1 + z1 * (hA[2 * q + 1] - n1);

            float2 zb = unpack2(gzB), azb = unpack2(accB[pz]);
            float2 nb = unpack2(gnB), anb = unpack2(accB[pn]);
            float z0b = sigmoid_f(zb.x + azb.x), z1b = sigmoid_f(zb.y + azb.y);
            float n0b = tanh_f(nb.x + rB[2 * q] * anb.x);
            float n1b = tanh_f(nb.y + rB[2 * q + 1] * anb.y);
            hB[2 * q]     = n0b + z0b * (hB[2 * q] - n0b);
            hB[2 * q + 1] = n1b + z1b * (hB[2 * q + 1] - n1b);
        }

        // sum logit for this step
        float sA = s_bs, sB = s_bs;
#pragma unroll
        for (int k = 0; k < HH; ++k) { sA += hA[k] * s_ws[k]; sB += hB[k] * s_ws[k]; }

        if (off_hid >= 0) {
            float4* poA = reinterpret_cast<float4*>(out + off_hid + ((size_t)eA * TT + t) * HH);
            float4* poB = reinterpret_cast<float4*>(out + off_hid + ((size_t)eB * TT + t) * HH);
            poA[0] = make_float4(hA[0],  hA[1],  hA[2],  hA[3]);
            poA[1] = make_float4(hA[4],  hA[5],  hA[6],  hA[7]);
            poA[2] = make_float4(hA[8],  hA[9],  hA[10], hA[11]);
            poA[3] = make_float4(hA[12], hA[13], hA[14], hA[15]);
            poB[0] = make_float4(hB[0],  hB[1],  hB[2],  hB[3]);
            poB[1] = make_float4(hB[4],  hB[5],  hB[6],  hB[7]);
            poB[2] = make_float4(hB[8],  hB[9],  hB[10], hB[11]);
            poB[3] = make_float4(hB[12], hB[13], hB[14], hB[15]);
        }
        if (off_sum >= 0) {
            out[off_sum + (size_t)eA * TT + t] = sA;
            out[off_sum + (size_t)eB * TT + t] = sB;
        }
        if (off_log >= 0) {
            out[off_log + (size_t)eA * (TT + 1) + t] = sA;
            out[off_log + (size_t)eB * (TT + 1) + t] = sB;
        }
    }

    float cA = s_bc, cB = s_bc;
#pragma unroll
    for (int k = 0; k < HH; ++k) { cA += hA[k] * s_wc[k]; cB += hB[k] * s_wc[k]; }
    if (off_car >= 0) { out[off_car + eA] = cA; out[off_car + eB] = cB; }
    if (off_log >= 0) {
        out[off_log + (size_t)eA * (TT + 1) + TT] = cA;
        out[off_log + (size_t)eB * (TT + 1) + TT] = cB;
    }
}

extern "C" void kernel_launch(void* const* d_in, const int* in_sizes, int n_in,
                              void* d_out, int out_size)
{
    const float* x       = (const float*)d_in[0];
    const float* w_ih    = (const float*)d_in[1];
    const float* w_hh    = (const float*)d_in[2];
    const float* b_ih    = (const float*)d_in[3];
    const float* b_hh    = (const float*)d_in[4];
    const float* w_sum   = (const float*)d_in[5];
    const float* b_sum   = (const float*)d_in[6];
    const float* w_carry = (const float*)d_in[7];
    const float* b_carry = (const float*)d_in[8];
    float* out = (float*)d_out;

    const long long HID = 0;
    const long long SUM = (long long)BATCH * TT * HH;              // 67108864
    const long long CAR = SUM + (long long)BATCH * TT;             // 71303168
    const long long LOG = CAR + (long long)BATCH;                  // 72351744
    const long long FULL = LOG + (long long)BATCH * (TT + 1);      // 77594624

    long long oh = -1, os = -1, oc = -1, ol = -1;
    long long sz = (long long)out_size;
    if (sz == FULL)                         { oh = HID; os = SUM; oc = CAR; ol = LOG; }
    else if (sz == (long long)BATCH * TT * HH)       { oh = 0; }
    else if (sz == (long long)BATCH * (TT + 1))      { ol = 0; }
    else if (sz == (long long)BATCH * TT)            { os = 0; }
    else if (sz == (long long)BATCH)                 { oc = 0; }
    else                                    { oh = HID; os = SUM; oc = CAR; ol = LOG; }

    const int blocks = BATCH / (THREADS * ELEMS);   // 2048
    gru_adder_kernel<<<blocks, THREADS>>>(x, w_ih, w_hh, b_ih, b_hh,
                                          w_sum, b_sum, w_carry, b_carry,
                                          out, oh, os, oc, ol);
}

// round 3
// speedup vs baseline: 1.0348x; 1.0348x over previous
#include <cuda_runtime.h>

// GRUAdder: B=1048576, T=4, I=2, H=16
// out = concat(hidden_table[B,4,16], sum_logits[B,4], carry[B,1], output_logits[B,5]) fp32

static constexpr int BATCH   = 1048576;
static constexpr int TT      = 4;
static constexpr int HH      = 16;
static constexpr int NG      = 48;   // 3*H gate outputs
static constexpr int KP      = 8;    // H/2 k-pairs
static constexpr int THREADS = 128;
static constexpr int ELEMS   = 2;

typedef unsigned long long u64;

__device__ __forceinline__ u64 pack2(float lo, float hi) {
    u64 r; asm("mov.b64 %0, {%1, %2};" : "=l"(r) : "f"(lo), "f"(hi)); return r;
}
__device__ __forceinline__ float2 unpack2(u64 v) {
    float2 f; asm("mov.b64 {%0, %1}, %2;" : "=f"(f.x), "=f"(f.y) : "l"(v)); return f;
}
__device__ __forceinline__ void ffma2(u64 &d, u64 a, u64 b) {
    asm("fma.rn.f32x2 %0, %1, %2, %0;" : "+l"(d) : "l"(a), "l"(b));
}
__device__ __forceinline__ float hsum2(u64 v) { float2 f = unpack2(v); return f.x + f.y; }
__device__ __forceinline__ float sigmoid_f(float x) {
    return __fdividef(1.0f, 1.0f + __expf(-x));
}
__device__ __forceinline__ float tanh_f(float x) {
    float e = __expf(2.0f * x);
    return __fdividef(e - 1.0f, e + 1.0f);
}

// One gate's pre-activation for both batch elements. Reads ONLY old h.
// IH: include input contribution. HHON: include hidden contribution.
template<bool IH, bool HHON>
__device__ __forceinline__ void gate2(const u64* __restrict__ wrow, u64 wih, float bias,
                                      u64 xpA, u64 xpB,
                                      const u64* h2A, const u64* h2B,
                                      float &gA, float &gB)
{
    u64 aA = pack2(bias, 0.0f);
    u64 aB = pack2(bias, 0.0f);
    if (IH) { ffma2(aA, wih, xpA); ffma2(aB, wih, xpB); }
    if (HHON) {
#pragma unroll
        for (int kk = 0; kk < KP; ++kk) {
            u64 w = wrow[kk];                 // one LDS.64 broadcast serves both elems
            ffma2(aA, w, h2A[kk]);
            ffma2(aB, w, h2B[kk]);
        }
    }
    gA = hsum2(aA);
    gB = hsum2(aB);
}

__global__ void __launch_bounds__(THREADS, 3)
gru_adder_kernel(const float* __restrict__ x,       // [B,4,2]
                 const float* __restrict__ w_ih,    // [48,2]
                 const float* __restrict__ w_hh,    // [48,16]
                 const float* __restrict__ b_ih,    // [48]
                 const float* __restrict__ b_hh,    // [48]
                 const float* __restrict__ w_sum,   // [16]
                 const float* __restrict__ b_sum,   // [1]
                 const float* __restrict__ w_carry, // [16]
                 const float* __restrict__ b_carry, // [1]
                 float* __restrict__ out,
                 long long off_hid, long long off_sum,
                 long long off_car, long long off_log)
{
    // weights pair-packed along K (hidden index) for f32x2
    __shared__ u64   s_whh2[NG][KP];  // {w_hh[g][2k], w_hh[g][2k+1]}
    __shared__ u64   s_wih2[NG];      // {w_ih[g][0], w_ih[g][1]}
    __shared__ float s_brz[32];       // b_ih[g] + b_hh[g], gates 0..31 (r,z)
    __shared__ float s_bin[16];       // b_ih[32+j]
    __shared__ float s_bhn[16];       // b_hh[32+j]
    __shared__ u64   s_ws2[KP], s_wc2[KP];
    __shared__ float s_bs, s_bc;

    const int tid = threadIdx.x;
    for (int i = tid; i < NG * KP; i += THREADS) {
        int g = i / KP, kk = i % KP;
        s_whh2[g][kk] = pack2(w_hh[g * HH + 2 * kk], w_hh[g * HH + 2 * kk + 1]);
    }
    if (tid < NG) s_wih2[tid] = pack2(w_ih[tid * 2], w_ih[tid * 2 + 1]);
    if (tid < 32) s_brz[tid] = b_ih[tid] + b_hh[tid];
    if (tid < 16) { s_bin[tid] = b_ih[32 + tid]; s_bhn[tid] = b_hh[32 + tid]; }
    if (tid < KP) {
        s_ws2[tid] = pack2(w_sum[2 * tid], w_sum[2 * tid + 1]);
        s_wc2[tid] = pack2(w_carry[2 * tid], w_carry[2 * tid + 1]);
    }
    if (tid == 0) { s_bs = b_sum[0]; s_bc = b_carry[0]; }
    __syncthreads();

    const int base = blockIdx.x * (THREADS * ELEMS) + tid;
    const int eA = base;
    const int eB = base + THREADS;

    const float4* xpA4 = reinterpret_cast<const float4*>(x + (size_t)eA * (TT * 2));
    const float4* xpB4 = reinterpret_cast<const float4*>(x + (size_t)eB * (TT * 2));
    float4 xA0 = xpA4[0], xA1 = xpA4[1];
    float4 xB0 = xpB4[0], xB1 = xpB4[1];
    u64 xpA[TT] = { pack2(xA0.x, xA0.y), pack2(xA0.z, xA0.w),
                    pack2(xA1.x, xA1.y), pack2(xA1.z, xA1.w) };
    u64 xpB[TT] = { pack2(xB0.x, xB0.y), pack2(xB0.z, xB0.w),
                    pack2(xB1.x, xB1.y), pack2(xB1.z, xB1.w) };

    u64 h2A[KP], h2B[KP];
#pragma unroll
    for (int kk = 0; kk < KP; ++kk) { h2A[kk] = 0ull; h2B[kk] = 0ull; }

#pragma unroll
    for (int t = 0; t < TT; ++t) {
        const u64 xA = xpA[t], xB = xpB[t];
        const bool hh_on = (t != 0);   // folds at compile time (t-loop unrolled)

        u64 hnA2[KP], hnB2[KP];        // NEW h, built separately — old h untouched
#pragma unroll
        for (int jj = 0; jj < KP; ++jj) {
            float hnA[2], hnB[2];
            float2 hoA = unpack2(h2A[jj]);
            float2 hoB = unpack2(h2B[jj]);
#pragma unroll
            for (int u = 0; u < 2; ++u) {
                const int j = 2 * jj + u;
                float grA, grB, gzA, gzB, niA, niB, nhA, nhB;
                if (hh_on) {
                    gate2<true,  true >(s_whh2[j],      s_wih2[j],      s_brz[j],
                                        xA, xB, h2A, h2B, grA, grB);
                    gate2<true,  true >(s_whh2[16 + j], s_wih2[16 + j], s_brz[16 + j],
                                        xA, xB, h2A, h2B, gzA, gzB);
                    gate2<true,  false>(nullptr,        s_wih2[32 + j], s_bin[j],
                                        xA, xB, h2A, h2B, niA, niB);
                    gate2<false, true >(s_whh2[32 + j], 0ull,           s_bhn[j],
                                        xA, xB, h2A, h2B, nhA, nhB);
                } else {
                    gate2<true,  false>(nullptr, s_wih2[j],      s_brz[j],      xA, xB, h2A, h2B, grA, grB);
                    gate2<true,  false>(nullptr, s_wih2[16 + j], s_brz[16 + j], xA, xB, h2A, h2B, gzA, gzB);
                    gate2<true,  false>(nullptr, s_wih2[32 + j], s_bin[j],      xA, xB, h2A, h2B, niA, niB);
                    nhA = s_bhn[j]; nhB = s_bhn[j];
                }
                float rA = sigmoid_f(grA), rB = sigmoid_f(grB);
                float zA = sigmoid_f(gzA), zB = sigmoid_f(gzB);
                float nA = tanh_f(niA + rA * nhA);
                float nB = tanh_f(niB + rB * nhB);
                float hA = (u == 0) ? hoA.x : hoA.y;
                float hB = (u == 0) ? hoB.x : hoB.y;
                hnA[u] = nA + zA * (hA - nA);
                hnB[u] = nB + zB * (hB - nB);
            }
            hnA2[jj] = pack2(hnA[0], hnA[1]);
            hnB2[jj] = pack2(hnB[0], hnB[1]);
        }

        // commit the step AFTER all gates consumed old h
#pragma unroll
        for (int kk = 0; kk < KP; ++kk) { h2A[kk] = hnA2[kk]; h2B[kk] = hnB2[kk]; }

        // sum logit for this step (uses updated h)
        u64 sa = pack2(s_bs, 0.0f), sb = pack2(s_bs, 0.0f);
#pragma unroll
        for (int kk = 0; kk < KP; ++kk) {
            u64 w = s_ws2[kk];
            ffma2(sa, w, h2A[kk]);
            ffma2(sb, w, h2B[kk]);
        }
        float sA = hsum2(sa), sB = hsum2(sb);

        if (off_hid >= 0) {
            float4* poA = reinterpret_cast<float4*>(out + off_hid + ((size_t)eA * TT + t) * HH);
            float4* poB = reinterpret_cast<float4*>(out + off_hid + ((size_t)eB * TT + t) * HH);
#pragma unroll
            for (int q = 0; q < 4; ++q) {
                float2 a0 = unpack2(h2A[2 * q]), a1 = unpack2(h2A[2 * q + 1]);
                poA[q] = make_float4(a0.x, a0.y, a1.x, a1.y);
            }
#pragma unroll
            for (int q = 0; q < 4; ++q) {
                float2 b0 = unpack2(h2B[2 * q]), b1 = unpack2(h2B[2 * q + 1]);
                poB[q] = make_float4(b0.x, b0.y, b1.x, b1.y);
            }
        }
        if (off_sum >= 0) {
            out[off_sum + (size_t)eA * TT + t] = sA;
            out[off_sum + (size_t)eB * TT + t] = sB;
        }
        if (off_log >= 0) {
            out[off_log + (size_t)eA * (TT + 1) + t] = sA;
            out[off_log + (size_t)eB * (TT + 1) + t] = sB;
        }
    }

    // carry head
    u64 ca = pack2(s_bc, 0.0f), cb = pack2(s_bc, 0.0f);
#pragma unroll
    for (int kk = 0; kk < KP; ++kk) {
        u64 w = s_wc2[kk];
        ffma2(ca, w, h2A[kk]);
        ffma2(cb, w, h2B[kk]);
    }
    float cA = hsum2(ca), cB = hsum2(cb);
    if (off_car >= 0) { out[off_car + eA] = cA; out[off_car + eB] = cB; }
    if (off_log >= 0) {
        out[off_log + (size_t)eA * (TT + 1) + TT] = cA;
        out[off_log + (size_t)eB * (TT + 1) + TT] = cB;
    }
}

extern "C" void kernel_launch(void* const* d_in, const int* in_sizes, int n_in,
                              void* d_out, int out_size)
{
    const float* x       = (const float*)d_in[0];
    const float* w_ih    = (const float*)d_in[1];
    const float* w_hh    = (const float*)d_in[2];
    const float* b_ih    = (const float*)d_in[3];
    const float* b_hh    = (const float*)d_in[4];
    const float* w_sum   = (const float*)d_in[5];
    const float* b_sum   = (const float*)d_in[6];
    const float* w_carry = (const float*)d_in[7];
    const float* b_carry = (const float*)d_in[8];
    float* out = (float*)d_out;

    const long long HID = 0;
    const long long SUM = (long long)BATCH * TT * HH;          // 67108864
    const long long CAR = SUM + (long long)BATCH * TT;         // 71303168
    const long long LOG = CAR + (long long)BATCH;              // 72351744
    const long long FULL = LOG + (long long)BATCH * (TT + 1);  // 77594624

    long long oh = -1, os = -1, oc = -1, ol = -1;
    long long sz = (long long)out_size;
    if (sz == FULL)                               { oh = HID; os = SUM; oc = CAR; ol = LOG; }
    else if (sz == (long long)BATCH * TT * HH)    { oh = 0; }
    else if (sz == (long long)BATCH * (TT + 1))   { ol = 0; }
    else if (sz == (long long)BATCH * TT)         { os = 0; }
    else if (sz == (long long)BATCH)              { oc = 0; }
    else                                          { oh = HID; os = SUM; oc = CAR; ol = LOG; }

    const int blocks = BATCH / (THREADS * ELEMS);   // 4096
    gru_adder_kernel<<<blocks, THREADS>>>(x, w_ih, w_hh, b_ih, b_hh,
                                          w_sum, b_sum, w_carry, b_carry,
                                          out, oh, os, oc, ol);
}